// round 1
// baseline (speedup 1.0000x reference)
#include <cuda_runtime.h>
#include <cuda_bf16.h>
#include <math.h>

// ---------------- problem constants ----------------
#define S_LEN   256
#define H_DIM   4096
#define NH      128
#define P_DIM   64
#define G_GRP   8
#define N_STATE 128
#define K_CONV  4
#define D_INNER 8192            // NH*P
#define D_STATE 1024            // G*N
#define CONV_DIM 10240          // D_INNER + 2*D_STATE
#define IN_OUT  18560           // D_INNER + CONV_DIM + NH
#define EPSV    1e-6f

#define OUT_HID  0
#define OUT_CONV 1048576
#define OUT_SSM  1079296

// ---------------- scratch (no allocations allowed) ----------------
__device__ float g_h[S_LEN * H_DIM];          // rmsnorm output
__device__ float g_proj[S_LEN * IN_OUT];      // in-proj output
__device__ float g_y[S_LEN * CONV_DIM];       // conv+silu output (x | B | C)
__device__ float g_dtp[S_LEN * NH];           // softplus(dt + bias)
__device__ float g_ys[S_LEN * D_INNER];       // scan output + D*x
__device__ float g_normed[S_LEN * D_INNER];   // gated group-norm output

// ---------------- helpers ----------------
__device__ __forceinline__ unsigned f2tf(float x) {
    unsigned u;
    asm("cvt.rna.tf32.f32 %0, %1;" : "=r"(u) : "f"(x));
    return u;
}

__device__ __forceinline__ void mma_tf32(float* c, const unsigned* a, const unsigned* b) {
    asm volatile(
        "mma.sync.aligned.m16n8k8.row.col.f32.tf32.tf32.f32 "
        "{%0,%1,%2,%3}, {%4,%5,%6,%7}, {%8,%9}, {%0,%1,%2,%3};"
        : "+f"(c[0]), "+f"(c[1]), "+f"(c[2]), "+f"(c[3])
        : "r"(a[0]), "r"(a[1]), "r"(a[2]), "r"(a[3]), "r"(b[0]), "r"(b[1]));
}

__device__ __forceinline__ void cp_async16(void* smem_dst, const void* gmem_src) {
    unsigned dst = (unsigned)__cvta_generic_to_shared(smem_dst);
    asm volatile("cp.async.cg.shared.global [%0], [%1], 16;" :: "r"(dst), "l"(gmem_src));
}
__device__ __forceinline__ void cp_async_commit() { asm volatile("cp.async.commit_group;"); }
template <int N>
__device__ __forceinline__ void cp_async_wait() { asm volatile("cp.async.wait_group %0;" :: "n"(N)); }

__device__ __forceinline__ float siluf(float x) { return x / (1.0f + expf(-x)); }
__device__ __forceinline__ float softplusf(float x) { return (x > 20.0f) ? x : log1pf(expf(x)); }

// ---------------- kernel 1: RMSNorm ----------------
__global__ void rmsnorm_kernel(const float* __restrict__ x, const float* __restrict__ w) {
    int t = blockIdx.x, tid = threadIdx.x;
    const float* row = x + (long)t * H_DIM;
    float v[16];
    float ss = 0.0f;
#pragma unroll
    for (int i = 0; i < 4; i++) {
        float4 f = *(const float4*)&row[tid * 4 + i * 1024];
        v[i * 4 + 0] = f.x; v[i * 4 + 1] = f.y; v[i * 4 + 2] = f.z; v[i * 4 + 3] = f.w;
        ss += f.x * f.x + f.y * f.y + f.z * f.z + f.w * f.w;
    }
    __shared__ float red[8];
    __shared__ float scale_sh;
#pragma unroll
    for (int o = 16; o; o >>= 1) ss += __shfl_xor_sync(0xffffffffu, ss, o);
    if ((tid & 31) == 0) red[tid >> 5] = ss;
    __syncthreads();
    if (tid == 0) {
        float s = 0.0f;
#pragma unroll
        for (int i = 0; i < 8; i++) s += red[i];
        scale_sh = rsqrtf(s / (float)H_DIM + EPSV);
    }
    __syncthreads();
    float sc = scale_sh;
#pragma unroll
    for (int i = 0; i < 4; i++) {
        int col = tid * 4 + i * 1024;
        float4 wf = *(const float4*)&w[col];
        float4 o;
        o.x = v[i * 4 + 0] * sc * wf.x;
        o.y = v[i * 4 + 1] * sc * wf.y;
        o.z = v[i * 4 + 2] * sc * wf.z;
        o.w = v[i * 4 + 3] * sc * wf.w;
        *(float4*)&g_h[(long)t * H_DIM + col] = o;
    }
}

// ---------------- GEMM: C[M,N] = A[M,K] * B[N,K]^T (+addend), tf32 mma ----------------
template <int BM, int BN, int WARPS_M, int WARPS_N>
__global__ void gemm_tf32_kernel(const float* __restrict__ A, const float* __restrict__ B,
                                 float* __restrict__ C, const float* __restrict__ addend,
                                 int M, int N, int K) {
    constexpr int BK  = 32;
    constexpr int LDS = BK + 4;        // pad to kill bank conflicts
    constexpr int WM  = BM / WARPS_M;
    constexpr int WN  = BN / WARPS_N;
    constexpr int MF  = WM / 16;
    constexpr int NF  = WN / 8;

    extern __shared__ float smem[];
    float* As = smem;                      // [2][BM][LDS]
    float* Bs = smem + 2 * BM * LDS;       // [2][BN][LDS]

    int tid = threadIdx.x;
    int wid = tid >> 5, lane = tid & 31;
    int g = lane >> 2, t4 = lane & 3;
    int wm = (wid % WARPS_M) * WM;
    int wn = (wid / WARPS_M) * WN;
    long m0 = (long)blockIdx.y * BM;
    long n0 = (long)blockIdx.x * BN;

    const float* Ablk = A + m0 * K;
    const float* Bblk = B + n0 * K;

    float acc[MF][NF][4];
#pragma unroll
    for (int i = 0; i < MF; i++)
#pragma unroll
        for (int j = 0; j < NF; j++)
#pragma unroll
            for (int r = 0; r < 4; r++) acc[i][j][r] = 0.0f;

    int KT = K / BK;

    // prologue: load tile 0 into stage 0
    {
        long k0 = 0;
#pragma unroll 2
        for (int idx = tid; idx < BM * 8; idx += 256) {
            int r = idx >> 3, qd = idx & 7;
            cp_async16(&As[r * LDS + qd * 4], Ablk + (long)r * K + k0 + qd * 4);
        }
#pragma unroll 2
        for (int idx = tid; idx < BN * 8; idx += 256) {
            int r = idx >> 3, qd = idx & 7;
            cp_async16(&Bs[r * LDS + qd * 4], Bblk + (long)r * K + k0 + qd * 4);
        }
        cp_async_commit();
    }

    for (int kt = 0; kt < KT; kt++) {
        int stage = kt & 1;
        if (kt + 1 < KT) {
            int ns = (kt + 1) & 1;
            long k0 = (long)(kt + 1) * BK;
            float* Ad = &As[ns * BM * LDS];
            float* Bd = &Bs[ns * BN * LDS];
#pragma unroll 2
            for (int idx = tid; idx < BM * 8; idx += 256) {
                int r = idx >> 3, qd = idx & 7;
                cp_async16(&Ad[r * LDS + qd * 4], Ablk + (long)r * K + k0 + qd * 4);
            }
#pragma unroll 2
            for (int idx = tid; idx < BN * 8; idx += 256) {
                int r = idx >> 3, qd = idx & 7;
                cp_async16(&Bd[r * LDS + qd * 4], Bblk + (long)r * K + k0 + qd * 4);
            }
            cp_async_commit();
            cp_async_wait<1>();
        } else {
            cp_async_wait<0>();
        }
        __syncthreads();

        const float* as = &As[stage * BM * LDS];
        const float* bs = &Bs[stage * BN * LDS];
#pragma unroll
        for (int ks = 0; ks < 4; ks++) {
            int k0 = ks * 8;
            unsigned af[MF][4], bf[NF][2];
#pragma unroll
            for (int mf = 0; mf < MF; mf++) {
                int r0 = wm + mf * 16 + g;
                af[mf][0] = f2tf(as[(r0)     * LDS + k0 + t4]);
                af[mf][1] = f2tf(as[(r0 + 8) * LDS + k0 + t4]);
                af[mf][2] = f2tf(as[(r0)     * LDS + k0 + t4 + 4]);
                af[mf][3] = f2tf(as[(r0 + 8) * LDS + k0 + t4 + 4]);
            }
#pragma unroll
            for (int nf = 0; nf < NF; nf++) {
                int r0 = wn + nf * 8 + g;
                bf[nf][0] = f2tf(bs[r0 * LDS + k0 + t4]);
                bf[nf][1] = f2tf(bs[r0 * LDS + k0 + t4 + 4]);
            }
#pragma unroll
            for (int mf = 0; mf < MF; mf++)
#pragma unroll
                for (int nf = 0; nf < NF; nf++)
                    mma_tf32(acc[mf][nf], af[mf], bf[nf]);
        }
        __syncthreads();
    }

    // epilogue
#pragma unroll
    for (int mf = 0; mf < MF; mf++) {
#pragma unroll
        for (int nf = 0; nf < NF; nf++) {
            long row = m0 + wm + mf * 16 + g;
            long col = n0 + wn + nf * 8 + t4 * 2;
            float2 v0 = make_float2(acc[mf][nf][0], acc[mf][nf][1]);
            float2 v1 = make_float2(acc[mf][nf][2], acc[mf][nf][3]);
            if (addend) {
                float2 a0 = *(const float2*)&addend[row * N + col];
                float2 a1 = *(const float2*)&addend[(row + 8) * N + col];
                v0.x += a0.x; v0.y += a0.y;
                v1.x += a1.x; v1.y += a1.y;
            }
            *(float2*)&C[row * N + col]       = v0;
            *(float2*)&C[(row + 8) * N + col] = v1;
        }
    }
}

// ---------------- kernel 3: depthwise conv (K=4) + SiLU + dtp + conv_state_out ----------------
__global__ void conv_kernel(const float* __restrict__ conv_state,
                            const float* __restrict__ conv_w,
                            const float* __restrict__ conv_b,
                            const float* __restrict__ dt_bias,
                            float* __restrict__ out_conv) {
    int t = blockIdx.x, tid = threadIdx.x;
    if (tid < NH) {
        float x = g_proj[(long)t * IN_OUT + (D_INNER + CONV_DIM) + tid] + dt_bias[tid];
        g_dtp[t * NH + tid] = softplusf(x);
    }
    for (int c = tid; c < CONV_DIM; c += 256) {
        float acc = conv_b[c];
#pragma unroll
        for (int j = 0; j < K_CONV; j++) {
            int idx = t + j;
            float v = (idx < K_CONV - 1)
                        ? conv_state[c * (K_CONV - 1) + idx]
                        : g_proj[(long)(idx - (K_CONV - 1)) * IN_OUT + D_INNER + c];
            acc += conv_w[c * K_CONV + j] * v;
        }
        g_y[(long)t * CONV_DIM + c] = siluf(acc);
        if (t >= S_LEN - (K_CONV - 1)) {
            out_conv[c * (K_CONV - 1) + (t - (S_LEN - (K_CONV - 1)))] =
                g_proj[(long)t * IN_OUT + D_INNER + c];
        }
    }
}

// ---------------- kernel 4: sequential SSM scan (one CTA per head) ----------------
__global__ void scan_kernel(const float* __restrict__ ssm_state_in,
                            const float* __restrict__ A_log,
                            const float* __restrict__ D_param,
                            float* __restrict__ out_ssm) {
    int h = blockIdx.x;
    int tid = threadIdx.x;
    int p = tid >> 2, q = tid & 3;
    int grp = h >> 4;                        // NH/G = 16 heads per group
    float A = -expf(A_log[h]);
    float Dp = D_param[h];

    float s[32];
    {
        const float* sin = ssm_state_in + (long)h * (P_DIM * N_STATE) + p * N_STATE + q * 32;
#pragma unroll
        for (int i = 0; i < 32; i += 4) {
            float4 f = *(const float4*)&sin[i];
            s[i] = f.x; s[i + 1] = f.y; s[i + 2] = f.z; s[i + 3] = f.w;
        }
    }

    for (int t = 0; t < S_LEN; t++) {
        long base = (long)t * CONV_DIM;
        float dtv = g_dtp[t * NH + h];
        float dA  = expf(dtv * A);
        float x   = g_y[base + h * P_DIM + p];
        float kx  = dtv * x;
        const float* Bp = g_y + base + D_INNER + grp * N_STATE + q * 32;
        const float* Cp = Bp + D_STATE;

        float a0 = 0.f, a1 = 0.f, a2 = 0.f, a3 = 0.f;
#pragma unroll
        for (int i = 0; i < 32; i += 4) {
            float4 b4 = *(const float4*)&Bp[i];
            float4 c4 = *(const float4*)&Cp[i];
            s[i]     = s[i]     * dA + kx * b4.x;  a0 += s[i]     * c4.x;
            s[i + 1] = s[i + 1] * dA + kx * b4.y;  a1 += s[i + 1] * c4.y;
            s[i + 2] = s[i + 2] * dA + kx * b4.z;  a2 += s[i + 2] * c4.z;
            s[i + 3] = s[i + 3] * dA + kx * b4.w;  a3 += s[i + 3] * c4.w;
        }
        float acc = (a0 + a1) + (a2 + a3);
        acc += __shfl_xor_sync(0xffffffffu, acc, 1);
        acc += __shfl_xor_sync(0xffffffffu, acc, 2);
        if (q == 0) g_ys[(long)t * D_INNER + h * P_DIM + p] = acc + Dp * x;
    }

    float* so = out_ssm + (long)h * (P_DIM * N_STATE) + p * N_STATE + q * 32;
#pragma unroll
    for (int i = 0; i < 32; i += 4)
        *(float4*)&so[i] = make_float4(s[i], s[i + 1], s[i + 2], s[i + 3]);
}

// ---------------- kernel 5: gate * silu + grouped RMSNorm ----------------
__global__ void gnorm_kernel(const float* __restrict__ w) {
    int t = blockIdx.x, tid = threadIdx.x;
    __shared__ float red[8];
    __shared__ float sc_sh;
    for (int grp = 0; grp < 8; grp++) {
        int d0 = grp * 1024 + tid * 4;
        float4 gate4 = *(const float4*)&g_proj[(long)t * IN_OUT + d0];
        float4 ys4   = *(const float4*)&g_ys[(long)t * D_INNER + d0];
        float gx = ys4.x * siluf(gate4.x);
        float gy = ys4.y * siluf(gate4.y);
        float gz = ys4.z * siluf(gate4.z);
        float gw = ys4.w * siluf(gate4.w);
        float ss = gx * gx + gy * gy + gz * gz + gw * gw;
#pragma unroll
        for (int o = 16; o; o >>= 1) ss += __shfl_xor_sync(0xffffffffu, ss, o);
        if ((tid & 31) == 0) red[tid >> 5] = ss;
        __syncthreads();
        if (tid == 0) {
            float s = 0.0f;
#pragma unroll
            for (int i = 0; i < 8; i++) s += red[i];
            sc_sh = rsqrtf(s / 1024.0f + EPSV);
        }
        __syncthreads();
        float sc = sc_sh;
        float4 wf = *(const float4*)&w[d0];
        float4 o;
        o.x = gx * sc * wf.x;
        o.y = gy * sc * wf.y;
        o.z = gz * sc * wf.z;
        o.w = gw * sc * wf.w;
        *(float4*)&g_normed[(long)t * D_INNER + d0] = o;
        __syncthreads();
    }
}

// ---------------- launch ----------------
extern "C" void kernel_launch(void* const* d_in, const int* in_sizes, int n_in,
                              void* d_out, int out_size) {
    const float* hidden     = (const float*)d_in[0];
    const float* conv_state = (const float*)d_in[1];
    const float* ssm_state  = (const float*)d_in[2];
    const float* norm_w     = (const float*)d_in[3];
    const float* w_in       = (const float*)d_in[4];
    const float* conv_w     = (const float*)d_in[5];
    const float* conv_b     = (const float*)d_in[6];
    const float* A_log      = (const float*)d_in[7];
    const float* D_param    = (const float*)d_in[8];
    const float* dt_bias    = (const float*)d_in[9];
    const float* ssm_nw     = (const float*)d_in[10];
    const float* w_out      = (const float*)d_in[11];
    float* out = (float*)d_out;

    // resolve scratch pointers (device symbols referenced directly in kernels)
    float* g_h_p;      cudaGetSymbolAddress((void**)&g_h_p, g_h);
    float* g_proj_p;   cudaGetSymbolAddress((void**)&g_proj_p, g_proj);
    float* g_normed_p; cudaGetSymbolAddress((void**)&g_normed_p, g_normed);

    constexpr int SMEM1 = 2 * (128 + 128) * 36 * 4;   // 73728
    constexpr int SMEM2 = 2 * (64 + 128) * 36 * 4;    // 55296
    cudaFuncSetAttribute(gemm_tf32_kernel<128, 128, 2, 4>,
                         cudaFuncAttributeMaxDynamicSharedMemorySize, SMEM1);
    cudaFuncSetAttribute(gemm_tf32_kernel<64, 128, 2, 4>,
                         cudaFuncAttributeMaxDynamicSharedMemorySize, SMEM2);

    // 1) RMSNorm
    rmsnorm_kernel<<<S_LEN, 256>>>(hidden, norm_w);

    // 2) in-proj: proj[256,18560] = h[256,4096] @ w_in^T
    gemm_tf32_kernel<128, 128, 2, 4><<<dim3(IN_OUT / 128, S_LEN / 128), 256, SMEM1>>>(
        g_h_p, w_in, g_proj_p, nullptr, S_LEN, IN_OUT, H_DIM);

    // 3) conv + silu + dtp + conv_state_out
    conv_kernel<<<S_LEN, 256>>>(conv_state, conv_w, conv_b, dt_bias, out + OUT_CONV);

    // 4) SSM scan (+ ssm_state_out)
    scan_kernel<<<NH, 256>>>(ssm_state, A_log, D_param, out + OUT_SSM);

    // 5) gate + group norm
    gnorm_kernel<<<S_LEN, 256>>>(ssm_nw);

    // 6) out-proj + residual: out[256,4096] = hidden + normed @ w_out^T
    gemm_tf32_kernel<64, 128, 2, 4><<<dim3(H_DIM / 128, S_LEN / 64), 256, SMEM2>>>(
        g_normed_p, w_out, out + OUT_HID, hidden, S_LEN, H_DIM, D_INNER);
}

// round 2
// speedup vs baseline: 1.0185x; 1.0185x over previous
#include <cuda_runtime.h>
#include <cuda_bf16.h>
#include <math.h>

// ---------------- problem constants ----------------
#define S_LEN   256
#define H_DIM   4096
#define NH      128
#define P_DIM   64
#define G_GRP   8
#define N_STATE 128
#define K_CONV  4
#define D_INNER 8192            // NH*P
#define D_STATE 1024            // G*N
#define CONV_DIM 10240          // D_INNER + 2*D_STATE
#define IN_OUT  18560           // D_INNER + CONV_DIM + NH
#define EPSV    1e-6f

#define NC      8               // chunks
#define CHUNK   32              // S_LEN / NC

#define OUT_HID  0
#define OUT_CONV 1048576
#define OUT_SSM  1079296

// ---------------- scratch (no allocations allowed) ----------------
__device__ float g_h[S_LEN * H_DIM];          // rmsnorm output
__device__ float g_proj[S_LEN * IN_OUT];      // in-proj output
__device__ float g_y[S_LEN * CONV_DIM];       // conv+silu output (x | B | C)
__device__ float g_dtp[S_LEN * NH];           // softplus(dt + bias)
__device__ float g_ys[S_LEN * D_INNER];       // scan output (local) then final
__device__ float g_normed[S_LEN * D_INNER];   // gated group-norm output
__device__ float g_cs[NC * NH * P_DIM * N_STATE]; // chunk local states -> chunk input states
__device__ float g_decay[S_LEN * NH];         // within-chunk decay prefix

// ---------------- helpers ----------------
__device__ __forceinline__ unsigned f2tf(float x) {
    unsigned u;
    asm("cvt.rna.tf32.f32 %0, %1;" : "=r"(u) : "f"(x));
    return u;
}

__device__ __forceinline__ void mma_tf32(float* c, const unsigned* a, const unsigned* b) {
    asm volatile(
        "mma.sync.aligned.m16n8k8.row.col.f32.tf32.tf32.f32 "
        "{%0,%1,%2,%3}, {%4,%5,%6,%7}, {%8,%9}, {%0,%1,%2,%3};"
        : "+f"(c[0]), "+f"(c[1]), "+f"(c[2]), "+f"(c[3])
        : "r"(a[0]), "r"(a[1]), "r"(a[2]), "r"(a[3]), "r"(b[0]), "r"(b[1]));
}

__device__ __forceinline__ void cp_async16(void* smem_dst, const void* gmem_src) {
    unsigned dst = (unsigned)__cvta_generic_to_shared(smem_dst);
    asm volatile("cp.async.cg.shared.global [%0], [%1], 16;" :: "r"(dst), "l"(gmem_src));
}
__device__ __forceinline__ void cp_async_commit() { asm volatile("cp.async.commit_group;"); }
template <int N>
__device__ __forceinline__ void cp_async_wait() { asm volatile("cp.async.wait_group %0;" :: "n"(N)); }

__device__ __forceinline__ float siluf(float x) { return x / (1.0f + expf(-x)); }
__device__ __forceinline__ float softplusf(float x) { return (x > 20.0f) ? x : log1pf(expf(x)); }

// ---------------- kernel 1: RMSNorm ----------------
__global__ void rmsnorm_kernel(const float* __restrict__ x, const float* __restrict__ w) {
    int t = blockIdx.x, tid = threadIdx.x;
    const float* row = x + (long)t * H_DIM;
    float v[16];
    float ss = 0.0f;
#pragma unroll
    for (int i = 0; i < 4; i++) {
        float4 f = *(const float4*)&row[tid * 4 + i * 1024];
        v[i * 4 + 0] = f.x; v[i * 4 + 1] = f.y; v[i * 4 + 2] = f.z; v[i * 4 + 3] = f.w;
        ss += f.x * f.x + f.y * f.y + f.z * f.z + f.w * f.w;
    }
    __shared__ float red[8];
    __shared__ float scale_sh;
#pragma unroll
    for (int o = 16; o; o >>= 1) ss += __shfl_xor_sync(0xffffffffu, ss, o);
    if ((tid & 31) == 0) red[tid >> 5] = ss;
    __syncthreads();
    if (tid == 0) {
        float s = 0.0f;
#pragma unroll
        for (int i = 0; i < 8; i++) s += red[i];
        scale_sh = rsqrtf(s / (float)H_DIM + EPSV);
    }
    __syncthreads();
    float sc = scale_sh;
#pragma unroll
    for (int i = 0; i < 4; i++) {
        int col = tid * 4 + i * 1024;
        float4 wf = *(const float4*)&w[col];
        float4 o;
        o.x = v[i * 4 + 0] * sc * wf.x;
        o.y = v[i * 4 + 1] * sc * wf.y;
        o.z = v[i * 4 + 2] * sc * wf.z;
        o.w = v[i * 4 + 3] * sc * wf.w;
        *(float4*)&g_h[(long)t * H_DIM + col] = o;
    }
}

// ---------------- GEMM: C[M,N] = A[M,K] * B[N,K]^T (+addend), tf32 mma ----------------
template <int BM, int BN, int WARPS_M, int WARPS_N>
__global__ void gemm_tf32_kernel(const float* __restrict__ A, const float* __restrict__ B,
                                 float* __restrict__ C, const float* __restrict__ addend,
                                 int M, int N, int K) {
    constexpr int BK  = 32;
    constexpr int LDS = BK + 4;
    constexpr int WM  = BM / WARPS_M;
    constexpr int WN  = BN / WARPS_N;
    constexpr int MF  = WM / 16;
    constexpr int NF  = WN / 8;

    extern __shared__ float smem[];
    float* As = smem;
    float* Bs = smem + 2 * BM * LDS;

    int tid = threadIdx.x;
    int wid = tid >> 5, lane = tid & 31;
    int g = lane >> 2, t4 = lane & 3;
    int wm = (wid % WARPS_M) * WM;
    int wn = (wid / WARPS_M) * WN;
    long m0 = (long)blockIdx.y * BM;
    long n0 = (long)blockIdx.x * BN;

    const float* Ablk = A + m0 * K;
    const float* Bblk = B + n0 * K;

    float acc[MF][NF][4];
#pragma unroll
    for (int i = 0; i < MF; i++)
#pragma unroll
        for (int j = 0; j < NF; j++)
#pragma unroll
            for (int r = 0; r < 4; r++) acc[i][j][r] = 0.0f;

    int KT = K / BK;

    {
        long k0 = 0;
#pragma unroll 2
        for (int idx = tid; idx < BM * 8; idx += 256) {
            int r = idx >> 3, qd = idx & 7;
            cp_async16(&As[r * LDS + qd * 4], Ablk + (long)r * K + k0 + qd * 4);
        }
#pragma unroll 2
        for (int idx = tid; idx < BN * 8; idx += 256) {
            int r = idx >> 3, qd = idx & 7;
            cp_async16(&Bs[r * LDS + qd * 4], Bblk + (long)r * K + k0 + qd * 4);
        }
        cp_async_commit();
    }

    for (int kt = 0; kt < KT; kt++) {
        int stage = kt & 1;
        if (kt + 1 < KT) {
            int ns = (kt + 1) & 1;
            long k0 = (long)(kt + 1) * BK;
            float* Ad = &As[ns * BM * LDS];
            float* Bd = &Bs[ns * BN * LDS];
#pragma unroll 2
            for (int idx = tid; idx < BM * 8; idx += 256) {
                int r = idx >> 3, qd = idx & 7;
                cp_async16(&Ad[r * LDS + qd * 4], Ablk + (long)r * K + k0 + qd * 4);
            }
#pragma unroll 2
            for (int idx = tid; idx < BN * 8; idx += 256) {
                int r = idx >> 3, qd = idx & 7;
                cp_async16(&Bd[r * LDS + qd * 4], Bblk + (long)r * K + k0 + qd * 4);
            }
            cp_async_commit();
            cp_async_wait<1>();
        } else {
            cp_async_wait<0>();
        }
        __syncthreads();

        const float* as = &As[stage * BM * LDS];
        const float* bs = &Bs[stage * BN * LDS];
#pragma unroll
        for (int ks = 0; ks < 4; ks++) {
            int k0 = ks * 8;
            unsigned af[MF][4], bf[NF][2];
#pragma unroll
            for (int mf = 0; mf < MF; mf++) {
                int r0 = wm + mf * 16 + g;
                af[mf][0] = f2tf(as[(r0)     * LDS + k0 + t4]);
                af[mf][1] = f2tf(as[(r0 + 8) * LDS + k0 + t4]);
                af[mf][2] = f2tf(as[(r0)     * LDS + k0 + t4 + 4]);
                af[mf][3] = f2tf(as[(r0 + 8) * LDS + k0 + t4 + 4]);
            }
#pragma unroll
            for (int nf = 0; nf < NF; nf++) {
                int r0 = wn + nf * 8 + g;
                bf[nf][0] = f2tf(bs[r0 * LDS + k0 + t4]);
                bf[nf][1] = f2tf(bs[r0 * LDS + k0 + t4 + 4]);
            }
#pragma unroll
            for (int mf = 0; mf < MF; mf++)
#pragma unroll
                for (int nf = 0; nf < NF; nf++)
                    mma_tf32(acc[mf][nf], af[mf], bf[nf]);
        }
        __syncthreads();
    }

#pragma unroll
    for (int mf = 0; mf < MF; mf++) {
#pragma unroll
        for (int nf = 0; nf < NF; nf++) {
            long row = m0 + wm + mf * 16 + g;
            long col = n0 + wn + nf * 8 + t4 * 2;
            float2 v0 = make_float2(acc[mf][nf][0], acc[mf][nf][1]);
            float2 v1 = make_float2(acc[mf][nf][2], acc[mf][nf][3]);
            if (addend) {
                float2 a0 = *(const float2*)&addend[row * N + col];
                float2 a1 = *(const float2*)&addend[(row + 8) * N + col];
                v0.x += a0.x; v0.y += a0.y;
                v1.x += a1.x; v1.y += a1.y;
            }
            *(float2*)&C[row * N + col]       = v0;
            *(float2*)&C[(row + 8) * N + col] = v1;
        }
    }
}

// ---------------- kernel 3: depthwise conv (K=4) + SiLU + dtp + conv_state_out ----------------
__global__ void conv_kernel(const float* __restrict__ conv_state,
                            const float* __restrict__ conv_w,
                            const float* __restrict__ conv_b,
                            const float* __restrict__ dt_bias,
                            float* __restrict__ out_conv) {
    int t = blockIdx.x, tid = threadIdx.x;
    if (tid < NH) {
        float x = g_proj[(long)t * IN_OUT + (D_INNER + CONV_DIM) + tid] + dt_bias[tid];
        g_dtp[t * NH + tid] = softplusf(x);
    }
    for (int c = tid; c < CONV_DIM; c += 256) {
        float acc = conv_b[c];
#pragma unroll
        for (int j = 0; j < K_CONV; j++) {
            int idx = t + j;
            float v = (idx < K_CONV - 1)
                        ? conv_state[c * (K_CONV - 1) + idx]
                        : g_proj[(long)(idx - (K_CONV - 1)) * IN_OUT + D_INNER + c];
            acc += conv_w[c * K_CONV + j] * v;
        }
        g_y[(long)t * CONV_DIM + c] = siluf(acc);
        if (t >= S_LEN - (K_CONV - 1)) {
            out_conv[c * (K_CONV - 1) + (t - (S_LEN - (K_CONV - 1)))] =
                g_proj[(long)t * IN_OUT + D_INNER + c];
        }
    }
}

// ---------------- kernel 4a: per-chunk local scan (zero initial state) ----------------
__global__ void scan_local_kernel(const float* __restrict__ A_log,
                                  const float* __restrict__ D_param) {
    int h = blockIdx.x;
    int c = blockIdx.y;
    int tid = threadIdx.x;
    int p = tid >> 2, q = tid & 3;
    int grp = h >> 4;
    float A = -expf(A_log[h]);
    float Dp = D_param[h];

    float s[32];
#pragma unroll
    for (int i = 0; i < 32; i++) s[i] = 0.0f;
    float decay = 1.0f;

    for (int tt = 0; tt < CHUNK; tt++) {
        int t = c * CHUNK + tt;
        long base = (long)t * CONV_DIM;
        float dtv = g_dtp[t * NH + h];
        float dA = expf(dtv * A);
        decay *= dA;
        if (tid == 0) g_decay[t * NH + h] = decay;
        float x = g_y[base + h * P_DIM + p];
        float kx = dtv * x;
        const float* Bp = g_y + base + D_INNER + grp * N_STATE + q * 32;
        const float* Cp = Bp + D_STATE;

        float a0 = 0.f, a1 = 0.f, a2 = 0.f, a3 = 0.f;
#pragma unroll
        for (int i = 0; i < 32; i += 4) {
            float4 b4 = *(const float4*)&Bp[i];
            float4 c4 = *(const float4*)&Cp[i];
            s[i]     = s[i]     * dA + kx * b4.x;  a0 += s[i]     * c4.x;
            s[i + 1] = s[i + 1] * dA + kx * b4.y;  a1 += s[i + 1] * c4.y;
            s[i + 2] = s[i + 2] * dA + kx * b4.z;  a2 += s[i + 2] * c4.z;
            s[i + 3] = s[i + 3] * dA + kx * b4.w;  a3 += s[i + 3] * c4.w;
        }
        float acc = (a0 + a1) + (a2 + a3);
        acc += __shfl_xor_sync(0xffffffffu, acc, 1);
        acc += __shfl_xor_sync(0xffffffffu, acc, 2);
        if (q == 0) g_ys[(long)t * D_INNER + h * P_DIM + p] = acc + Dp * x;
    }

    // chunk-local final state
    float* so = g_cs + (long)c * (NH * P_DIM * N_STATE) + (long)h * (P_DIM * N_STATE)
                + p * N_STATE + q * 32;
#pragma unroll
    for (int i = 0; i < 32; i += 4)
        *(float4*)&so[i] = make_float4(s[i], s[i + 1], s[i + 2], s[i + 3]);
}

// ---------------- kernel 4b: propagate chunk-boundary states ----------------
// After this, g_cs[c] holds the INPUT state of chunk c; writes final ssm_state.
__global__ void chunk_prop_kernel(const float* __restrict__ ssm_state_in,
                                  float* __restrict__ out_ssm) {
    long idx4 = (long)blockIdx.x * 256 + threadIdx.x;   // over float4s: 1048576/4
    long idx = idx4 * 4;
    int h = (int)(idx >> 13);                           // 8192 floats per head
    float4 s = *(const float4*)&ssm_state_in[idx];
#pragma unroll
    for (int c = 0; c < NC; c++) {
        float alpha = g_decay[(c * CHUNK + CHUNK - 1) * NH + h];
        float4 loc = *(const float4*)&g_cs[(long)c * 1048576 + idx];
        *(float4*)&g_cs[(long)c * 1048576 + idx] = s;   // s_in(c)
        s.x = alpha * s.x + loc.x;
        s.y = alpha * s.y + loc.y;
        s.z = alpha * s.z + loc.z;
        s.w = alpha * s.w + loc.w;
    }
    *(float4*)&out_ssm[idx] = s;
}

// ---------------- kernel 4c: correction y_t += decay(t) * C_t . s_in(chunk) ----------------
#define SP_STR 129
__global__ void chunk_corr_kernel() {
    int h = blockIdx.x;
    int c = blockIdx.y;
    int tid = threadIdx.x;
    int grp = h >> 4;

    extern __shared__ float sm[];
    float* S  = sm;                        // [64][SP_STR]
    float* Cs = sm + P_DIM * SP_STR;       // [32][128]
    float* Dec = Cs + CHUNK * N_STATE;     // [32]

    // load s_in (g_cs slot c): 8192 floats
    {
        const float* src = g_cs + (long)c * 1048576 + (long)h * (P_DIM * N_STATE);
        for (int i = tid; i < 2048; i += 256) {
            int pp = i >> 5, n4 = (i & 31) * 4;
            float4 v = *(const float4*)&src[pp * N_STATE + n4];
            float* d = &S[pp * SP_STR + n4];
            d[0] = v.x; d[1] = v.y; d[2] = v.z; d[3] = v.w;
        }
    }
    // load C rows: 32 x 128
    for (int i = tid; i < 1024; i += 256) {
        int tt = i >> 5, n4 = (i & 31) * 4;
        long base = (long)(c * CHUNK + tt) * CONV_DIM + D_INNER + D_STATE
                    + grp * N_STATE + n4;
        *(float4*)&Cs[tt * N_STATE + n4] = *(const float4*)&g_y[base];
    }
    if (tid < CHUNK) Dec[tid] = g_decay[(c * CHUNK + tid) * NH + h];
    __syncthreads();

    int p = tid & 63;
    int tb = (tid >> 6) * 8;    // 8 t's per thread
    float acc[8];
#pragma unroll
    for (int j = 0; j < 8; j++) acc[j] = 0.0f;

    const float* Sp = &S[p * SP_STR];
#pragma unroll 4
    for (int n = 0; n < N_STATE; n += 4) {
        float s0 = Sp[n], s1 = Sp[n + 1], s2 = Sp[n + 2], s3 = Sp[n + 3];
#pragma unroll
        for (int j = 0; j < 8; j++) {
            float4 c4 = *(const float4*)&Cs[(tb + j) * N_STATE + n];
            acc[j] += s0 * c4.x + s1 * c4.y + s2 * c4.z + s3 * c4.w;
        }
    }
#pragma unroll
    for (int j = 0; j < 8; j++) {
        int t = c * CHUNK + tb + j;
        long o = (long)t * D_INNER + h * P_DIM + p;
        g_ys[o] += Dec[tb + j] * acc[j];
    }
}

// ---------------- kernel 5: gate * silu + grouped RMSNorm ----------------
__global__ void gnorm_kernel(const float* __restrict__ w) {
    int t = blockIdx.x, tid = threadIdx.x;
    __shared__ float red[8];
    __shared__ float sc_sh;
    for (int grp = 0; grp < 8; grp++) {
        int d0 = grp * 1024 + tid * 4;
        float4 gate4 = *(const float4*)&g_proj[(long)t * IN_OUT + d0];
        float4 ys4   = *(const float4*)&g_ys[(long)t * D_INNER + d0];
        float gx = ys4.x * siluf(gate4.x);
        float gy = ys4.y * siluf(gate4.y);
        float gz = ys4.z * siluf(gate4.z);
        float gw = ys4.w * siluf(gate4.w);
        float ss = gx * gx + gy * gy + gz * gz + gw * gw;
#pragma unroll
        for (int o = 16; o; o >>= 1) ss += __shfl_xor_sync(0xffffffffu, ss, o);
        if ((tid & 31) == 0) red[tid >> 5] = ss;
        __syncthreads();
        if (tid == 0) {
            float s = 0.0f;
#pragma unroll
            for (int i = 0; i < 8; i++) s += red[i];
            sc_sh = rsqrtf(s / 1024.0f + EPSV);
        }
        __syncthreads();
        float sc = sc_sh;
        float4 wf = *(const float4*)&w[d0];
        float4 o;
        o.x = gx * sc * wf.x;
        o.y = gy * sc * wf.y;
        o.z = gz * sc * wf.z;
        o.w = gw * sc * wf.w;
        *(float4*)&g_normed[(long)t * D_INNER + d0] = o;
        __syncthreads();
    }
}

// ---------------- launch ----------------
extern "C" void kernel_launch(void* const* d_in, const int* in_sizes, int n_in,
                              void* d_out, int out_size) {
    const float* hidden     = (const float*)d_in[0];
    const float* conv_state = (const float*)d_in[1];
    const float* ssm_state  = (const float*)d_in[2];
    const float* norm_w     = (const float*)d_in[3];
    const float* w_in       = (const float*)d_in[4];
    const float* conv_w     = (const float*)d_in[5];
    const float* conv_b     = (const float*)d_in[6];
    const float* A_log      = (const float*)d_in[7];
    const float* D_param    = (const float*)d_in[8];
    const float* dt_bias    = (const float*)d_in[9];
    const float* ssm_nw     = (const float*)d_in[10];
    const float* w_out      = (const float*)d_in[11];
    float* out = (float*)d_out;

    float* g_h_p;      cudaGetSymbolAddress((void**)&g_h_p, g_h);
    float* g_proj_p;   cudaGetSymbolAddress((void**)&g_proj_p, g_proj);
    float* g_normed_p; cudaGetSymbolAddress((void**)&g_normed_p, g_normed);

    constexpr int SMEM1 = 2 * (128 + 128) * 36 * 4;   // 73728
    constexpr int SMEM2 = 2 * (64 + 128) * 36 * 4;    // 55296
    constexpr int SMEM_CORR = (P_DIM * SP_STR + CHUNK * N_STATE + CHUNK) * 4; // ~49.7KB
    cudaFuncSetAttribute(gemm_tf32_kernel<128, 128, 2, 4>,
                         cudaFuncAttributeMaxDynamicSharedMemorySize, SMEM1);
    cudaFuncSetAttribute(gemm_tf32_kernel<64, 128, 2, 4>,
                         cudaFuncAttributeMaxDynamicSharedMemorySize, SMEM2);
    cudaFuncSetAttribute(chunk_corr_kernel,
                         cudaFuncAttributeMaxDynamicSharedMemorySize, SMEM_CORR);

    // 1) RMSNorm
    rmsnorm_kernel<<<S_LEN, 256>>>(hidden, norm_w);

    // 2) in-proj
    gemm_tf32_kernel<128, 128, 2, 4><<<dim3(IN_OUT / 128, S_LEN / 128), 256, SMEM1>>>(
        g_h_p, w_in, g_proj_p, nullptr, S_LEN, IN_OUT, H_DIM);

    // 3) conv + silu + dtp + conv_state_out
    conv_kernel<<<S_LEN, 256>>>(conv_state, conv_w, conv_b, dt_bias, out + OUT_CONV);

    // 4) chunked SSM scan
    scan_local_kernel<<<dim3(NH, NC), 256>>>(A_log, D_param);
    chunk_prop_kernel<<<1024, 256>>>(ssm_state, out + OUT_SSM);
    chunk_corr_kernel<<<dim3(NH, NC), 256, SMEM_CORR>>>();

    // 5) gate + group norm
    gnorm_kernel<<<S_LEN, 256>>>(ssm_nw);

    // 6) out-proj + residual
    gemm_tf32_kernel<64, 128, 2, 4><<<dim3(H_DIM / 128, S_LEN / 64), 256, SMEM2>>>(
        g_normed_p, w_out, out + OUT_HID, hidden, S_LEN, H_DIM, D_INNER);
}

// round 8
// speedup vs baseline: 1.2035x; 1.1817x over previous
#include <cuda_runtime.h>
#include <cuda_bf16.h>
#include <math.h>

// ---------------- problem constants ----------------
#define S_LEN   256
#define H_DIM   4096
#define NH      128
#define P_DIM   64
#define G_GRP   8
#define N_STATE 128
#define K_CONV  4
#define D_INNER 8192            // NH*P
#define D_STATE 1024            // G*N
#define CONV_DIM 10240          // D_INNER + 2*D_STATE
#define IN_OUT  18560           // D_INNER + CONV_DIM + NH
#define EPSV    1e-6f

#define NC      8               // chunks
#define CHUNK   32              // S_LEN / NC

#define OUT_HID  0
#define OUT_CONV 1048576
#define OUT_SSM  1079296

// ---------------- scratch (no allocations allowed) ----------------
__device__ float g_h[S_LEN * H_DIM];          // rmsnorm output
__device__ float g_proj[S_LEN * IN_OUT];      // in-proj output
__device__ float g_y[S_LEN * CONV_DIM];       // conv+silu output (x | B | C)
__device__ float g_dtp[S_LEN * NH];           // softplus(dt + bias)
__device__ float g_ys[S_LEN * D_INNER];       // scan output (local) then final
__device__ float g_normed[S_LEN * D_INNER];   // gated group-norm output
__device__ float g_cs[NC * NH * P_DIM * N_STATE]; // chunk states
__device__ float g_decay[S_LEN * NH];         // within-chunk decay prefix exp(A*cdt)

// ---------------- helpers ----------------
__device__ __forceinline__ unsigned f2tf(float x) {
    unsigned u;
    asm("cvt.rna.tf32.f32 %0, %1;" : "=r"(u) : "f"(x));
    return u;
}

__device__ __forceinline__ void mma_tf32(float* c, const unsigned* a, const unsigned* b) {
    asm volatile(
        "mma.sync.aligned.m16n8k8.row.col.f32.tf32.tf32.f32 "
        "{%0,%1,%2,%3}, {%4,%5,%6,%7}, {%8,%9}, {%0,%1,%2,%3};"
        : "+f"(c[0]), "+f"(c[1]), "+f"(c[2]), "+f"(c[3])
        : "r"(a[0]), "r"(a[1]), "r"(a[2]), "r"(a[3]), "r"(b[0]), "r"(b[1]));
}

__device__ __forceinline__ void cp_async16(void* smem_dst, const void* gmem_src) {
    unsigned dst = (unsigned)__cvta_generic_to_shared(smem_dst);
    asm volatile("cp.async.cg.shared.global [%0], [%1], 16;" :: "r"(dst), "l"(gmem_src));
}
__device__ __forceinline__ void cp_async_commit() { asm volatile("cp.async.commit_group;"); }
template <int N>
__device__ __forceinline__ void cp_async_wait() { asm volatile("cp.async.wait_group %0;" :: "n"(N)); }

__device__ __forceinline__ float siluf(float x) { return x / (1.0f + expf(-x)); }
__device__ __forceinline__ float softplusf(float x) { return (x > 20.0f) ? x : log1pf(expf(x)); }

// ---------------- kernel 1: RMSNorm ----------------
__global__ void rmsnorm_kernel(const float* __restrict__ x, const float* __restrict__ w) {
    int t = blockIdx.x, tid = threadIdx.x;
    const float* row = x + (long)t * H_DIM;
    float v[16];
    float ss = 0.0f;
#pragma unroll
    for (int i = 0; i < 4; i++) {
        float4 f = *(const float4*)&row[tid * 4 + i * 1024];
        v[i * 4 + 0] = f.x; v[i * 4 + 1] = f.y; v[i * 4 + 2] = f.z; v[i * 4 + 3] = f.w;
        ss += f.x * f.x + f.y * f.y + f.z * f.z + f.w * f.w;
    }
    __shared__ float red[8];
    __shared__ float scale_sh;
#pragma unroll
    for (int o = 16; o; o >>= 1) ss += __shfl_xor_sync(0xffffffffu, ss, o);
    if ((tid & 31) == 0) red[tid >> 5] = ss;
    __syncthreads();
    if (tid == 0) {
        float s = 0.0f;
#pragma unroll
        for (int i = 0; i < 8; i++) s += red[i];
        scale_sh = rsqrtf(s / (float)H_DIM + EPSV);
    }
    __syncthreads();
    float sc = scale_sh;
#pragma unroll
    for (int i = 0; i < 4; i++) {
        int col = tid * 4 + i * 1024;
        float4 wf = *(const float4*)&w[col];
        float4 o;
        o.x = v[i * 4 + 0] * sc * wf.x;
        o.y = v[i * 4 + 1] * sc * wf.y;
        o.z = v[i * 4 + 2] * sc * wf.z;
        o.w = v[i * 4 + 3] * sc * wf.w;
        *(float4*)&g_h[(long)t * H_DIM + col] = o;
    }
}

// ---------------- GEMM: C[M,N] = A[M,K] * B[N,K]^T (+addend), legacy tf32 mma ----------------
template <int BM, int BN, int WARPS_M, int WARPS_N>
__global__ void gemm_tf32_kernel(const float* __restrict__ A, const float* __restrict__ B,
                                 float* __restrict__ C, const float* __restrict__ addend,
                                 int M, int N, int K) {
    constexpr int BK  = 32;
    constexpr int LDS = BK + 4;
    constexpr int WM  = BM / WARPS_M;
    constexpr int WN  = BN / WARPS_N;
    constexpr int MF  = WM / 16;
    constexpr int NF  = WN / 8;

    extern __shared__ float smem[];
    float* As = smem;
    float* Bs = smem + 2 * BM * LDS;

    int tid = threadIdx.x;
    int wid = tid >> 5, lane = tid & 31;
    int g = lane >> 2, t4 = lane & 3;
    int wm = (wid % WARPS_M) * WM;
    int wn = (wid / WARPS_M) * WN;
    long m0 = (long)blockIdx.y * BM;
    long n0 = (long)blockIdx.x * BN;

    const float* Ablk = A + m0 * K;
    const float* Bblk = B + n0 * K;

    float acc[MF][NF][4];
#pragma unroll
    for (int i = 0; i < MF; i++)
#pragma unroll
        for (int j = 0; j < NF; j++)
#pragma unroll
            for (int r = 0; r < 4; r++) acc[i][j][r] = 0.0f;

    int KT = K / BK;

    {
        long k0 = 0;
#pragma unroll 2
        for (int idx = tid; idx < BM * 8; idx += 256) {
            int r = idx >> 3, qd = idx & 7;
            cp_async16(&As[r * LDS + qd * 4], Ablk + (long)r * K + k0 + qd * 4);
        }
#pragma unroll 2
        for (int idx = tid; idx < BN * 8; idx += 256) {
            int r = idx >> 3, qd = idx & 7;
            cp_async16(&Bs[r * LDS + qd * 4], Bblk + (long)r * K + k0 + qd * 4);
        }
        cp_async_commit();
    }

    for (int kt = 0; kt < KT; kt++) {
        int stage = kt & 1;
        if (kt + 1 < KT) {
            int ns = (kt + 1) & 1;
            long k0 = (long)(kt + 1) * BK;
            float* Ad = &As[ns * BM * LDS];
            float* Bd = &Bs[ns * BN * LDS];
#pragma unroll 2
            for (int idx = tid; idx < BM * 8; idx += 256) {
                int r = idx >> 3, qd = idx & 7;
                cp_async16(&Ad[r * LDS + qd * 4], Ablk + (long)r * K + k0 + qd * 4);
            }
#pragma unroll 2
            for (int idx = tid; idx < BN * 8; idx += 256) {
                int r = idx >> 3, qd = idx & 7;
                cp_async16(&Bd[r * LDS + qd * 4], Bblk + (long)r * K + k0 + qd * 4);
            }
            cp_async_commit();
            cp_async_wait<1>();
        } else {
            cp_async_wait<0>();
        }
        __syncthreads();

        const float* as = &As[stage * BM * LDS];
        const float* bs = &Bs[stage * BN * LDS];
#pragma unroll
        for (int ks = 0; ks < 4; ks++) {
            int k0 = ks * 8;
            unsigned af[MF][4], bf[NF][2];
#pragma unroll
            for (int mf = 0; mf < MF; mf++) {
                int r0 = wm + mf * 16 + g;
                af[mf][0] = f2tf(as[(r0)     * LDS + k0 + t4]);
                af[mf][1] = f2tf(as[(r0 + 8) * LDS + k0 + t4]);
                af[mf][2] = f2tf(as[(r0)     * LDS + k0 + t4 + 4]);
                af[mf][3] = f2tf(as[(r0 + 8) * LDS + k0 + t4 + 4]);
            }
#pragma unroll
            for (int nf = 0; nf < NF; nf++) {
                int r0 = wn + nf * 8 + g;
                bf[nf][0] = f2tf(bs[r0 * LDS + k0 + t4]);
                bf[nf][1] = f2tf(bs[r0 * LDS + k0 + t4 + 4]);
            }
#pragma unroll
            for (int mf = 0; mf < MF; mf++)
#pragma unroll
                for (int nf = 0; nf < NF; nf++)
                    mma_tf32(acc[mf][nf], af[mf], bf[nf]);
        }
        __syncthreads();
    }

#pragma unroll
    for (int mf = 0; mf < MF; mf++) {
#pragma unroll
        for (int nf = 0; nf < NF; nf++) {
            long row = m0 + wm + mf * 16 + g;
            long col = n0 + wn + nf * 8 + t4 * 2;
            float2 v0 = make_float2(acc[mf][nf][0], acc[mf][nf][1]);
            float2 v1 = make_float2(acc[mf][nf][2], acc[mf][nf][3]);
            if (addend) {
                float2 a0 = *(const float2*)&addend[row * N + col];
                float2 a1 = *(const float2*)&addend[(row + 8) * N + col];
                v0.x += a0.x; v0.y += a0.y;
                v1.x += a1.x; v1.y += a1.y;
            }
            *(float2*)&C[row * N + col]       = v0;
            *(float2*)&C[(row + 8) * N + col] = v1;
        }
    }
}

// ---------------- kernel 3: depthwise conv (K=4) + SiLU + dtp + conv_state_out ----------------
__global__ void conv_kernel(const float* __restrict__ conv_state,
                            const float* __restrict__ conv_w,
                            const float* __restrict__ conv_b,
                            const float* __restrict__ dt_bias,
                            float* __restrict__ out_conv) {
    int t = blockIdx.x, tid = threadIdx.x;
    if (tid < NH) {
        float x = g_proj[(long)t * IN_OUT + (D_INNER + CONV_DIM) + tid] + dt_bias[tid];
        g_dtp[t * NH + tid] = softplusf(x);
    }
    for (int c = tid; c < CONV_DIM; c += 256) {
        float acc = conv_b[c];
#pragma unroll
        for (int j = 0; j < K_CONV; j++) {
            int idx = t + j;
            float v = (idx < K_CONV - 1)
                        ? conv_state[c * (K_CONV - 1) + idx]
                        : g_proj[(long)(idx - (K_CONV - 1)) * IN_OUT + D_INNER + c];
            acc += conv_w[c * K_CONV + j] * v;
        }
        g_y[(long)t * CONV_DIM + c] = siluf(acc);
        if (t >= S_LEN - (K_CONV - 1)) {
            out_conv[c * (K_CONV - 1) + (t - (S_LEN - (K_CONV - 1)))] =
                g_proj[(long)t * IN_OUT + D_INNER + c];
        }
    }
}

// ---------------- kernel 4a: chunk-parallel local "scan" (Mamba2 chunked form) ----------------
#define BST 132
__global__ void scan_chunk_kernel(const float* __restrict__ A_log,
                                  const float* __restrict__ D_param) {
    int h = blockIdx.x;
    int c = blockIdx.y;
    int tid = threadIdx.x;
    int grp = h >> 4;
    float A = -expf(A_log[h]);
    float Dp = D_param[h];

    __shared__ float Bs[CHUNK * BST];
    __shared__ float Cs[CHUNK * BST];
    __shared__ float Xs[CHUNK * P_DIM];
    __shared__ float Ms[CHUNK * (CHUNK + 1)];
    __shared__ float dts[CHUNK], cdt[CHUNK], wc[CHUNK];

    if (tid < CHUNK) {
        float v = g_dtp[(c * CHUNK + tid) * NH + h];
        dts[tid] = v;
#pragma unroll
        for (int off = 1; off < CHUNK; off <<= 1) {
            float n = __shfl_up_sync(0xffffffffu, v, off);
            if ((tid & 31) >= off) v += n;
        }
        cdt[tid] = v;
    }

    for (int i = tid; i < CHUNK * 32; i += 256) {
        int row = i >> 5, col = (i & 31) * 4;
        long base = (long)(c * CHUNK + row) * CONV_DIM + D_INNER + grp * N_STATE + col;
        *(float4*)&Bs[row * BST + col] = *(const float4*)&g_y[base];
        *(float4*)&Cs[row * BST + col] = *(const float4*)&g_y[base + D_STATE];
    }
    for (int i = tid; i < CHUNK * 16; i += 256) {
        int row = i >> 4, col = (i & 15) * 4;
        long base = (long)(c * CHUNK + row) * CONV_DIM + h * P_DIM + col;
        *(float4*)&Xs[row * P_DIM + col] = *(const float4*)&g_y[base];
    }
    __syncthreads();

    if (tid < CHUNK) {
        float cde = cdt[CHUNK - 1];
        wc[tid] = expf(A * (cde - cdt[tid])) * dts[tid];
        g_decay[(c * CHUNK + tid) * NH + h] = expf(A * cdt[tid]);
    }

    {
        int t0 = (tid >> 4) * 2, u0 = (tid & 15) * 2;
        float g00 = 0.f, g01 = 0.f, g10 = 0.f, g11 = 0.f;
        const float* c0 = &Cs[t0 * BST];
        const float* c1 = &Cs[(t0 + 1) * BST];
        const float* b0 = &Bs[u0 * BST];
        const float* b1 = &Bs[(u0 + 1) * BST];
#pragma unroll 8
        for (int k = 0; k < N_STATE; k += 4) {
            float4 cv0 = *(const float4*)&c0[k];
            float4 cv1 = *(const float4*)&c1[k];
            float4 bv0 = *(const float4*)&b0[k];
            float4 bv1 = *(const float4*)&b1[k];
            g00 += cv0.x * bv0.x + cv0.y * bv0.y + cv0.z * bv0.z + cv0.w * bv0.w;
            g01 += cv0.x * bv1.x + cv0.y * bv1.y + cv0.z * bv1.z + cv0.w * bv1.w;
            g10 += cv1.x * bv0.x + cv1.y * bv0.y + cv1.z * bv0.z + cv1.w * bv0.w;
            g11 += cv1.x * bv1.x + cv1.y * bv1.y + cv1.z * bv1.z + cv1.w * bv1.w;
        }
#pragma unroll
        for (int a = 0; a < 2; a++)
#pragma unroll
            for (int b = 0; b < 2; b++) {
                int t = t0 + a, u = u0 + b;
                float gv = (a == 0) ? (b == 0 ? g00 : g01) : (b == 0 ? g10 : g11);
                float m = (u <= t) ? expf(A * (cdt[t] - cdt[u])) * dts[u] * gv : 0.0f;
                Ms[t * (CHUNK + 1) + u] = m;
            }
    }
    __syncthreads();

    {
        int t = tid >> 3, p0 = (tid & 7) * 8;
        float acc[8];
#pragma unroll
        for (int j = 0; j < 8; j++) acc[j] = 0.0f;
        const float* mrow = &Ms[t * (CHUNK + 1)];
#pragma unroll 8
        for (int u = 0; u <= t; u++) {
            float m = mrow[u];
            float4 x0 = *(const float4*)&Xs[u * P_DIM + p0];
            float4 x1 = *(const float4*)&Xs[u * P_DIM + p0 + 4];
            acc[0] += m * x0.x; acc[1] += m * x0.y; acc[2] += m * x0.z; acc[3] += m * x0.w;
            acc[4] += m * x1.x; acc[5] += m * x1.y; acc[6] += m * x1.z; acc[7] += m * x1.w;
        }
        float4 xt0 = *(const float4*)&Xs[t * P_DIM + p0];
        float4 xt1 = *(const float4*)&Xs[t * P_DIM + p0 + 4];
        float4 o0 = make_float4(acc[0] + Dp * xt0.x, acc[1] + Dp * xt0.y,
                                acc[2] + Dp * xt0.z, acc[3] + Dp * xt0.w);
        float4 o1 = make_float4(acc[4] + Dp * xt1.x, acc[5] + Dp * xt1.y,
                                acc[6] + Dp * xt1.z, acc[7] + Dp * xt1.w);
        long o = (long)(c * CHUNK + t) * D_INNER + h * P_DIM + p0;
        *(float4*)&g_ys[o] = o0;
        *(float4*)&g_ys[o + 4] = o1;
    }

    {
        int p = tid >> 2, n0 = (tid & 3) * 32;
        float acc[32];
#pragma unroll
        for (int k = 0; k < 32; k++) acc[k] = 0.0f;
#pragma unroll 4
        for (int u = 0; u < CHUNK; u++) {
            float xw = Xs[u * P_DIM + p] * wc[u];
            const float* brow = &Bs[u * BST + n0];
#pragma unroll
            for (int k = 0; k < 32; k += 4) {
                float4 bv = *(const float4*)&brow[k];
                acc[k]     += xw * bv.x;
                acc[k + 1] += xw * bv.y;
                acc[k + 2] += xw * bv.z;
                acc[k + 3] += xw * bv.w;
            }
        }
        float* so = g_cs + (long)c * (NH * P_DIM * N_STATE) + (long)h * (P_DIM * N_STATE)
                    + p * N_STATE + n0;
#pragma unroll
        for (int k = 0; k < 32; k += 4)
            *(float4*)&so[k] = make_float4(acc[k], acc[k + 1], acc[k + 2], acc[k + 3]);
    }
}

// ---------------- kernel 4b: propagate chunk-boundary states ----------------
__global__ void chunk_prop_kernel(const float* __restrict__ ssm_state_in,
                                  float* __restrict__ out_ssm) {
    long idx4 = (long)blockIdx.x * 256 + threadIdx.x;
    long idx = idx4 * 4;
    int h = (int)(idx >> 13);
    float4 s = *(const float4*)&ssm_state_in[idx];
#pragma unroll
    for (int c = 0; c < NC; c++) {
        float alpha = g_decay[(c * CHUNK + CHUNK - 1) * NH + h];
        float4 loc = *(const float4*)&g_cs[(long)c * 1048576 + idx];
        *(float4*)&g_cs[(long)c * 1048576 + idx] = s;
        s.x = alpha * s.x + loc.x;
        s.y = alpha * s.y + loc.y;
        s.z = alpha * s.z + loc.z;
        s.w = alpha * s.w + loc.w;
    }
    *(float4*)&out_ssm[idx] = s;
}

// ---------------- kernel 4c: correction y_t += decay(t) * C_t . s_in(chunk) ----------------
#define SP_STR 129
__global__ void chunk_corr_kernel() {
    int h = blockIdx.x;
    int c = blockIdx.y;
    int tid = threadIdx.x;
    int grp = h >> 4;

    extern __shared__ float sm[];
    float* S  = sm;                        // [64][SP_STR]
    float* Cs = sm + P_DIM * SP_STR;       // [32][128]
    float* Dec = Cs + CHUNK * N_STATE;     // [32]

    {
        const float* src = g_cs + (long)c * 1048576 + (long)h * (P_DIM * N_STATE);
        for (int i = tid; i < 2048; i += 256) {
            int pp = i >> 5, n4 = (i & 31) * 4;
            float4 v = *(const float4*)&src[pp * N_STATE + n4];
            float* d = &S[pp * SP_STR + n4];
            d[0] = v.x; d[1] = v.y; d[2] = v.z; d[3] = v.w;
        }
    }
    for (int i = tid; i < 1024; i += 256) {
        int tt = i >> 5, n4 = (i & 31) * 4;
        long base = (long)(c * CHUNK + tt) * CONV_DIM + D_INNER + D_STATE
                    + grp * N_STATE + n4;
        *(float4*)&Cs[tt * N_STATE + n4] = *(const float4*)&g_y[base];
    }
    if (tid < CHUNK) Dec[tid] = g_decay[(c * CHUNK + tid) * NH + h];
    __syncthreads();

    int p = tid & 63;
    int tb = (tid >> 6) * 8;
    float acc[8];
#pragma unroll
    for (int j = 0; j < 8; j++) acc[j] = 0.0f;

    const float* Sp = &S[p * SP_STR];
#pragma unroll 4
    for (int n = 0; n < N_STATE; n += 4) {
        float s0 = Sp[n], s1 = Sp[n + 1], s2 = Sp[n + 2], s3 = Sp[n + 3];
#pragma unroll
        for (int j = 0; j < 8; j++) {
            float4 c4 = *(const float4*)&Cs[(tb + j) * N_STATE + n];
            acc[j] += s0 * c4.x + s1 * c4.y + s2 * c4.z + s3 * c4.w;
        }
    }
#pragma unroll
    for (int j = 0; j < 8; j++) {
        int t = c * CHUNK + tb + j;
        long o = (long)t * D_INNER + h * P_DIM + p;
        g_ys[o] += Dec[tb + j] * acc[j];
    }
}

// ---------------- kernel 5: gate * silu + grouped RMSNorm ----------------
__global__ void gnorm_kernel(const float* __restrict__ w) {
    int t = blockIdx.x, tid = threadIdx.x;
    __shared__ float red[8];
    __shared__ float sc_sh;
    for (int grp = 0; grp < 8; grp++) {
        int d0 = grp * 1024 + tid * 4;
        float4 gate4 = *(const float4*)&g_proj[(long)t * IN_OUT + d0];
        float4 ys4   = *(const float4*)&g_ys[(long)t * D_INNER + d0];
        float gx = ys4.x * siluf(gate4.x);
        float gy = ys4.y * siluf(gate4.y);
        float gz = ys4.z * siluf(gate4.z);
        float gw = ys4.w * siluf(gate4.w);
        float ss = gx * gx + gy * gy + gz * gz + gw * gw;
#pragma unroll
        for (int o = 16; o; o >>= 1) ss += __shfl_xor_sync(0xffffffffu, ss, o);
        if ((tid & 31) == 0) red[tid >> 5] = ss;
        __syncthreads();
        if (tid == 0) {
            float s = 0.0f;
#pragma unroll
            for (int i = 0; i < 8; i++) s += red[i];
            sc_sh = rsqrtf(s / 1024.0f + EPSV);
        }
        __syncthreads();
        float sc = sc_sh;
        float4 wf = *(const float4*)&w[d0];
        float4 o;
        o.x = gx * sc * wf.x;
        o.y = gy * sc * wf.y;
        o.z = gz * sc * wf.z;
        o.w = gw * sc * wf.w;
        *(float4*)&g_normed[(long)t * D_INNER + d0] = o;
        __syncthreads();
    }
}

// ---------------- launch ----------------
extern "C" void kernel_launch(void* const* d_in, const int* in_sizes, int n_in,
                              void* d_out, int out_size) {
    const float* hidden     = (const float*)d_in[0];
    const float* conv_state = (const float*)d_in[1];
    const float* ssm_state  = (const float*)d_in[2];
    const float* norm_w     = (const float*)d_in[3];
    const float* w_in       = (const float*)d_in[4];
    const float* conv_w     = (const float*)d_in[5];
    const float* conv_b     = (const float*)d_in[6];
    const float* A_log      = (const float*)d_in[7];
    const float* D_param    = (const float*)d_in[8];
    const float* dt_bias    = (const float*)d_in[9];
    const float* ssm_nw     = (const float*)d_in[10];
    const float* w_out      = (const float*)d_in[11];
    float* out = (float*)d_out;

    float* g_h_p;      cudaGetSymbolAddress((void**)&g_h_p, g_h);
    float* g_proj_p;   cudaGetSymbolAddress((void**)&g_proj_p, g_proj);
    float* g_normed_p; cudaGetSymbolAddress((void**)&g_normed_p, g_normed);

    constexpr int SMEM1 = 2 * (128 + 128) * 36 * 4;   // 73728
    constexpr int SMEM2 = 2 * (64 + 128) * 36 * 4;    // 55296
    constexpr int SMEM_CORR = (P_DIM * SP_STR + CHUNK * N_STATE + CHUNK) * 4;
    cudaFuncSetAttribute(gemm_tf32_kernel<128, 128, 2, 4>,
                         cudaFuncAttributeMaxDynamicSharedMemorySize, SMEM1);
    cudaFuncSetAttribute(gemm_tf32_kernel<64, 128, 2, 4>,
                         cudaFuncAttributeMaxDynamicSharedMemorySize, SMEM2);
    cudaFuncSetAttribute(chunk_corr_kernel,
                         cudaFuncAttributeMaxDynamicSharedMemorySize, SMEM_CORR);

    // 1) RMSNorm
    rmsnorm_kernel<<<S_LEN, 256>>>(hidden, norm_w);

    // 2) in-proj
    gemm_tf32_kernel<128, 128, 2, 4><<<dim3(IN_OUT / 128, S_LEN / 128), 256, SMEM1>>>(
        g_h_p, w_in, g_proj_p, nullptr, S_LEN, IN_OUT, H_DIM);

    // 3) conv + silu + dtp + conv_state_out
    conv_kernel<<<S_LEN, 256>>>(conv_state, conv_w, conv_b, dt_bias, out + OUT_CONV);

    // 4) chunked SSM
    scan_chunk_kernel<<<dim3(NH, NC), 256>>>(A_log, D_param);
    chunk_prop_kernel<<<1024, 256>>>(ssm_state, out + OUT_SSM);
    chunk_corr_kernel<<<dim3(NH, NC), 256, SMEM_CORR>>>();

    // 5) gate + group norm
    gnorm_kernel<<<S_LEN, 256>>>(ssm_nw);

    // 6) out-proj + residual
    gemm_tf32_kernel<64, 128, 2, 4><<<dim3(H_DIM / 128, S_LEN / 64), 256, SMEM2>>>(
        g_normed_p, w_out, out + OUT_HID, hidden, S_LEN, H_DIM, D_INNER);
}

// round 10
// speedup vs baseline: 1.5083x; 1.2532x over previous
#include <cuda_runtime.h>
#include <cuda_bf16.h>
#include <math.h>

// ---------------- problem constants ----------------
#define S_LEN   256
#define H_DIM   4096
#define NH      128
#define P_DIM   64
#define G_GRP   8
#define N_STATE 128
#define K_CONV  4
#define D_INNER 8192            // NH*P
#define D_STATE 1024            // G*N
#define CONV_DIM 10240          // D_INNER + 2*D_STATE
#define IN_OUT  18560           // D_INNER + CONV_DIM + NH
#define EPSV    1e-6f

#define NC      8               // chunks
#define CHUNK   32              // S_LEN / NC

#define OUT_HID  0
#define OUT_CONV 1048576
#define OUT_SSM  1079296

// ---------------- scratch (no allocations allowed) ----------------
__device__ float g_h[S_LEN * H_DIM];          // rmsnorm output (tf32-pre-rounded)
__device__ float g_proj[S_LEN * IN_OUT];      // in-proj output
__device__ float g_y[S_LEN * CONV_DIM];       // conv+silu output (x | B | C)
__device__ float g_dtp[S_LEN * NH];           // softplus(dt + bias)
__device__ float g_ys[S_LEN * D_INNER];       // scan output (local) then final
__device__ float g_normed[S_LEN * D_INNER];   // gated group-norm output (tf32-pre-rounded)
__device__ float g_cs[NC * NH * P_DIM * N_STATE]; // chunk states
__device__ float g_decay[S_LEN * NH];         // within-chunk decay prefix exp(A*cdt)

// ---------------- helpers ----------------
__device__ __forceinline__ unsigned f2tf(float x) {
    unsigned u;
    asm("cvt.rna.tf32.f32 %0, %1;" : "=r"(u) : "f"(x));
    return u;
}
__device__ __forceinline__ float f2tf_f(float x) { return __uint_as_float(f2tf(x)); }

__device__ __forceinline__ void mma_tf32(float* c, const unsigned* a, const unsigned* b) {
    asm volatile(
        "mma.sync.aligned.m16n8k8.row.col.f32.tf32.tf32.f32 "
        "{%0,%1,%2,%3}, {%4,%5,%6,%7}, {%8,%9}, {%0,%1,%2,%3};"
        : "+f"(c[0]), "+f"(c[1]), "+f"(c[2]), "+f"(c[3])
        : "r"(a[0]), "r"(a[1]), "r"(a[2]), "r"(a[3]), "r"(b[0]), "r"(b[1]));
}

__device__ __forceinline__ void cp_async16(void* smem_dst, const void* gmem_src) {
    unsigned dst = (unsigned)__cvta_generic_to_shared(smem_dst);
    asm volatile("cp.async.cg.shared.global [%0], [%1], 16;" :: "r"(dst), "l"(gmem_src));
}
__device__ __forceinline__ void cp_async_commit() { asm volatile("cp.async.commit_group;"); }
template <int N>
__device__ __forceinline__ void cp_async_wait() { asm volatile("cp.async.wait_group %0;" :: "n"(N)); }

__device__ __forceinline__ float siluf(float x) { return x / (1.0f + expf(-x)); }
__device__ __forceinline__ float softplusf(float x) { return (x > 20.0f) ? x : log1pf(expf(x)); }

// ---------------- kernel 1: RMSNorm (emits tf32-pre-rounded values) ----------------
__global__ void rmsnorm_kernel(const float* __restrict__ x, const float* __restrict__ w) {
    int t = blockIdx.x, tid = threadIdx.x;
    const float* row = x + (long)t * H_DIM;
    float v[16];
    float ss = 0.0f;
#pragma unroll
    for (int i = 0; i < 4; i++) {
        float4 f = *(const float4*)&row[tid * 4 + i * 1024];
        v[i * 4 + 0] = f.x; v[i * 4 + 1] = f.y; v[i * 4 + 2] = f.z; v[i * 4 + 3] = f.w;
        ss += f.x * f.x + f.y * f.y + f.z * f.z + f.w * f.w;
    }
    __shared__ float red[8];
    __shared__ float scale_sh;
#pragma unroll
    for (int o = 16; o; o >>= 1) ss += __shfl_xor_sync(0xffffffffu, ss, o);
    if ((tid & 31) == 0) red[tid >> 5] = ss;
    __syncthreads();
    if (tid == 0) {
        float s = 0.0f;
#pragma unroll
        for (int i = 0; i < 8; i++) s += red[i];
        scale_sh = rsqrtf(s / (float)H_DIM + EPSV);
    }
    __syncthreads();
    float sc = scale_sh;
#pragma unroll
    for (int i = 0; i < 4; i++) {
        int col = tid * 4 + i * 1024;
        float4 wf = *(const float4*)&w[col];
        float4 o;
        o.x = f2tf_f(v[i * 4 + 0] * sc * wf.x);
        o.y = f2tf_f(v[i * 4 + 1] * sc * wf.y);
        o.z = f2tf_f(v[i * 4 + 2] * sc * wf.z);
        o.w = f2tf_f(v[i * 4 + 3] * sc * wf.w);
        *(float4*)&g_h[(long)t * H_DIM + col] = o;
    }
}

// ---------------- GEMM: C[M,N] = A[M,K] * B[N,K]^T (+addend), legacy tf32 mma ----------------
// A is PRE-ROUNDED to tf32 by its producer: A fragments loaded raw (no cvt).
template <int BM, int BN, int WARPS_M, int WARPS_N>
__global__ void gemm_tf32_kernel(const float* __restrict__ A, const float* __restrict__ B,
                                 float* __restrict__ C, const float* __restrict__ addend,
                                 int M, int N, int K) {
    constexpr int BK  = 32;
    constexpr int LDS = BK + 4;
    constexpr int WM  = BM / WARPS_M;
    constexpr int WN  = BN / WARPS_N;
    constexpr int MF  = WM / 16;
    constexpr int NF  = WN / 8;

    extern __shared__ float smem[];
    float* As = smem;
    float* Bs = smem + 2 * BM * LDS;

    int tid = threadIdx.x;
    int wid = tid >> 5, lane = tid & 31;
    int g = lane >> 2, t4 = lane & 3;
    int wm = (wid % WARPS_M) * WM;
    int wn = (wid / WARPS_M) * WN;
    long m0 = (long)blockIdx.y * BM;
    long n0 = (long)blockIdx.x * BN;

    const float* Ablk = A + m0 * K;
    const float* Bblk = B + n0 * K;

    float acc[MF][NF][4];
#pragma unroll
    for (int i = 0; i < MF; i++)
#pragma unroll
        for (int j = 0; j < NF; j++)
#pragma unroll
            for (int r = 0; r < 4; r++) acc[i][j][r] = 0.0f;

    int KT = K / BK;

    {
        long k0 = 0;
#pragma unroll 2
        for (int idx = tid; idx < BM * 8; idx += 256) {
            int r = idx >> 3, qd = idx & 7;
            cp_async16(&As[r * LDS + qd * 4], Ablk + (long)r * K + k0 + qd * 4);
        }
#pragma unroll 2
        for (int idx = tid; idx < BN * 8; idx += 256) {
            int r = idx >> 3, qd = idx & 7;
            cp_async16(&Bs[r * LDS + qd * 4], Bblk + (long)r * K + k0 + qd * 4);
        }
        cp_async_commit();
    }

    for (int kt = 0; kt < KT; kt++) {
        int stage = kt & 1;
        if (kt + 1 < KT) {
            int ns = (kt + 1) & 1;
            long k0 = (long)(kt + 1) * BK;
            float* Ad = &As[ns * BM * LDS];
            float* Bd = &Bs[ns * BN * LDS];
#pragma unroll 2
            for (int idx = tid; idx < BM * 8; idx += 256) {
                int r = idx >> 3, qd = idx & 7;
                cp_async16(&Ad[r * LDS + qd * 4], Ablk + (long)r * K + k0 + qd * 4);
            }
#pragma unroll 2
            for (int idx = tid; idx < BN * 8; idx += 256) {
                int r = idx >> 3, qd = idx & 7;
                cp_async16(&Bd[r * LDS + qd * 4], Bblk + (long)r * K + k0 + qd * 4);
            }
            cp_async_commit();
            cp_async_wait<1>();
        } else {
            cp_async_wait<0>();
        }
        __syncthreads();

        const float* as = &As[stage * BM * LDS];
        const float* bs = &Bs[stage * BN * LDS];
#pragma unroll
        for (int ks = 0; ks < 4; ks++) {
            int k0 = ks * 8;
            unsigned af[MF][4], bf[NF][2];
#pragma unroll
            for (int mf = 0; mf < MF; mf++) {
                int r0 = wm + mf * 16 + g;
                af[mf][0] = __float_as_uint(as[(r0)     * LDS + k0 + t4]);
                af[mf][1] = __float_as_uint(as[(r0 + 8) * LDS + k0 + t4]);
                af[mf][2] = __float_as_uint(as[(r0)     * LDS + k0 + t4 + 4]);
                af[mf][3] = __float_as_uint(as[(r0 + 8) * LDS + k0 + t4 + 4]);
            }
#pragma unroll
            for (int nf = 0; nf < NF; nf++) {
                int r0 = wn + nf * 8 + g;
                bf[nf][0] = f2tf(bs[r0 * LDS + k0 + t4]);
                bf[nf][1] = f2tf(bs[r0 * LDS + k0 + t4 + 4]);
            }
#pragma unroll
            for (int mf = 0; mf < MF; mf++)
#pragma unroll
                for (int nf = 0; nf < NF; nf++)
                    mma_tf32(acc[mf][nf], af[mf], bf[nf]);
        }
        __syncthreads();
    }

#pragma unroll
    for (int mf = 0; mf < MF; mf++) {
#pragma unroll
        for (int nf = 0; nf < NF; nf++) {
            long row = m0 + wm + mf * 16 + g;
            long col = n0 + wn + nf * 8 + t4 * 2;
            float2 v0 = make_float2(acc[mf][nf][0], acc[mf][nf][1]);
            float2 v1 = make_float2(acc[mf][nf][2], acc[mf][nf][3]);
            if (addend) {
                float2 a0 = *(const float2*)&addend[row * N + col];
                float2 a1 = *(const float2*)&addend[(row + 8) * N + col];
                v0.x += a0.x; v0.y += a0.y;
                v1.x += a1.x; v1.y += a1.y;
            }
            *(float2*)&C[row * N + col]       = v0;
            *(float2*)&C[(row + 8) * N + col] = v1;
        }
    }
}

// ---------------- kernel 3: depthwise conv (K=4) + SiLU + dtp + conv_state_out ----------------
__global__ void conv_kernel(const float* __restrict__ conv_state,
                            const float* __restrict__ conv_w,
                            const float* __restrict__ conv_b,
                            const float* __restrict__ dt_bias,
                            float* __restrict__ out_conv) {
    int t = blockIdx.x, tid = threadIdx.x;
    if (tid < NH) {
        float x = g_proj[(long)t * IN_OUT + (D_INNER + CONV_DIM) + tid] + dt_bias[tid];
        g_dtp[t * NH + tid] = softplusf(x);
    }
    for (int c = tid; c < CONV_DIM; c += 256) {
        float acc = conv_b[c];
#pragma unroll
        for (int j = 0; j < K_CONV; j++) {
            int idx = t + j;
            float v = (idx < K_CONV - 1)
                        ? conv_state[c * (K_CONV - 1) + idx]
                        : g_proj[(long)(idx - (K_CONV - 1)) * IN_OUT + D_INNER + c];
            acc += conv_w[c * K_CONV + j] * v;
        }
        g_y[(long)t * CONV_DIM + c] = siluf(acc);
        if (t >= S_LEN - (K_CONV - 1)) {
            out_conv[c * (K_CONV - 1) + (t - (S_LEN - (K_CONV - 1)))] =
                g_proj[(long)t * IN_OUT + D_INNER + c];
        }
    }
}

// ---------------- kernel 4a: chunk-parallel local "scan" (Mamba2 chunked form) ----------------
#define BST 132
__global__ void scan_chunk_kernel(const float* __restrict__ A_log,
                                  const float* __restrict__ D_param) {
    int h = blockIdx.x;
    int c = blockIdx.y;
    int tid = threadIdx.x;
    int grp = h >> 4;
    float A = -expf(A_log[h]);
    float Dp = D_param[h];

    __shared__ float Bs[CHUNK * BST];
    __shared__ float Cs[CHUNK * BST];
    __shared__ float Xs[CHUNK * P_DIM];
    __shared__ float Ms[CHUNK * (CHUNK + 1)];
    __shared__ float dts[CHUNK], cdt[CHUNK], wc[CHUNK];

    if (tid < CHUNK) {
        float v = g_dtp[(c * CHUNK + tid) * NH + h];
        dts[tid] = v;
#pragma unroll
        for (int off = 1; off < CHUNK; off <<= 1) {
            float n = __shfl_up_sync(0xffffffffu, v, off);
            if ((tid & 31) >= off) v += n;
        }
        cdt[tid] = v;
    }

    for (int i = tid; i < CHUNK * 32; i += 256) {
        int row = i >> 5, col = (i & 31) * 4;
        long base = (long)(c * CHUNK + row) * CONV_DIM + D_INNER + grp * N_STATE + col;
        *(float4*)&Bs[row * BST + col] = *(const float4*)&g_y[base];
        *(float4*)&Cs[row * BST + col] = *(const float4*)&g_y[base + D_STATE];
    }
    for (int i = tid; i < CHUNK * 16; i += 256) {
        int row = i >> 4, col = (i & 15) * 4;
        long base = (long)(c * CHUNK + row) * CONV_DIM + h * P_DIM + col;
        *(float4*)&Xs[row * P_DIM + col] = *(const float4*)&g_y[base];
    }
    __syncthreads();

    if (tid < CHUNK) {
        float cde = cdt[CHUNK - 1];
        wc[tid] = expf(A * (cde - cdt[tid])) * dts[tid];
        g_decay[(c * CHUNK + tid) * NH + h] = expf(A * cdt[tid]);
    }

    // G + M: each thread computes a 2x2 block (C-rows broadcast across 16 lanes)
    {
        int t0 = (tid >> 4) * 2, u0 = (tid & 15) * 2;
        float g00 = 0.f, g01 = 0.f, g10 = 0.f, g11 = 0.f;
        const float* c0 = &Cs[t0 * BST];
        const float* c1 = &Cs[(t0 + 1) * BST];
        const float* b0 = &Bs[u0 * BST];
        const float* b1 = &Bs[(u0 + 1) * BST];
#pragma unroll 8
        for (int k = 0; k < N_STATE; k += 4) {
            float4 cv0 = *(const float4*)&c0[k];
            float4 cv1 = *(const float4*)&c1[k];
            float4 bv0 = *(const float4*)&b0[k];
            float4 bv1 = *(const float4*)&b1[k];
            g00 += cv0.x * bv0.x + cv0.y * bv0.y + cv0.z * bv0.z + cv0.w * bv0.w;
            g01 += cv0.x * bv1.x + cv0.y * bv1.y + cv0.z * bv1.z + cv0.w * bv1.w;
            g10 += cv1.x * bv0.x + cv1.y * bv0.y + cv1.z * bv0.z + cv1.w * bv0.w;
            g11 += cv1.x * bv1.x + cv1.y * bv1.y + cv1.z * bv1.z + cv1.w * bv1.w;
        }
#pragma unroll
        for (int a = 0; a < 2; a++)
#pragma unroll
            for (int b = 0; b < 2; b++) {
                int t = t0 + a, u = u0 + b;
                float gv = (a == 0) ? (b == 0 ? g00 : g01) : (b == 0 ? g10 : g11);
                float m = (u <= t) ? expf(A * (cdt[t] - cdt[u])) * dts[u] * gv : 0.0f;
                Ms[t * (CHUNK + 1) + u] = m;
            }
    }
    __syncthreads();

    // Y = M * X + D*X : thread -> (t = tid>>3, p0 = (tid&7)*8)
    {
        int t = tid >> 3, p0 = (tid & 7) * 8;
        float acc[8];
#pragma unroll
        for (int j = 0; j < 8; j++) acc[j] = 0.0f;
        const float* mrow = &Ms[t * (CHUNK + 1)];
#pragma unroll 8
        for (int u = 0; u <= t; u++) {
            float m = mrow[u];
            float4 x0 = *(const float4*)&Xs[u * P_DIM + p0];
            float4 x1 = *(const float4*)&Xs[u * P_DIM + p0 + 4];
            acc[0] += m * x0.x; acc[1] += m * x0.y; acc[2] += m * x0.z; acc[3] += m * x0.w;
            acc[4] += m * x1.x; acc[5] += m * x1.y; acc[6] += m * x1.z; acc[7] += m * x1.w;
        }
        float4 xt0 = *(const float4*)&Xs[t * P_DIM + p0];
        float4 xt1 = *(const float4*)&Xs[t * P_DIM + p0 + 4];
        float4 o0 = make_float4(acc[0] + Dp * xt0.x, acc[1] + Dp * xt0.y,
                                acc[2] + Dp * xt0.z, acc[3] + Dp * xt0.w);
        float4 o1 = make_float4(acc[4] + Dp * xt1.x, acc[5] + Dp * xt1.y,
                                acc[6] + Dp * xt1.z, acc[7] + Dp * xt1.w);
        long o = (long)(c * CHUNK + t) * D_INNER + h * P_DIM + p0;
        *(float4*)&g_ys[o] = o0;
        *(float4*)&g_ys[o + 4] = o1;
    }

    // S_local[p][n] = sum_u wc[u]*X[u][p]*B[u][n]
    // Register-blocked 4p x 8n per thread: p0 = (tid>>4)*4 (X broadcast across 16 lanes),
    // n0 = (tid&15)*8. Per u: 4 broadcast X scalars + 2 LDS.128 feed 32 FMAs.
    {
        int p0 = (tid >> 4) * 4;
        int n0 = (tid & 15) * 8;
        float acc[4][8];
#pragma unroll
        for (int i = 0; i < 4; i++)
#pragma unroll
            for (int j = 0; j < 8; j++) acc[i][j] = 0.0f;

#pragma unroll 4
        for (int u = 0; u < CHUNK; u++) {
            float w = wc[u];
            const float* xrow = &Xs[u * P_DIM + p0];
            float xw0 = xrow[0] * w;
            float xw1 = xrow[1] * w;
            float xw2 = xrow[2] * w;
            float xw3 = xrow[3] * w;
            float4 b0 = *(const float4*)&Bs[u * BST + n0];
            float4 b1 = *(const float4*)&Bs[u * BST + n0 + 4];
            acc[0][0] += xw0 * b0.x; acc[0][1] += xw0 * b0.y; acc[0][2] += xw0 * b0.z; acc[0][3] += xw0 * b0.w;
            acc[0][4] += xw0 * b1.x; acc[0][5] += xw0 * b1.y; acc[0][6] += xw0 * b1.z; acc[0][7] += xw0 * b1.w;
            acc[1][0] += xw1 * b0.x; acc[1][1] += xw1 * b0.y; acc[1][2] += xw1 * b0.z; acc[1][3] += xw1 * b0.w;
            acc[1][4] += xw1 * b1.x; acc[1][5] += xw1 * b1.y; acc[1][6] += xw1 * b1.z; acc[1][7] += xw1 * b1.w;
            acc[2][0] += xw2 * b0.x; acc[2][1] += xw2 * b0.y; acc[2][2] += xw2 * b0.z; acc[2][3] += xw2 * b0.w;
            acc[2][4] += xw2 * b1.x; acc[2][5] += xw2 * b1.y; acc[2][6] += xw2 * b1.z; acc[2][7] += xw2 * b1.w;
            acc[3][0] += xw3 * b0.x; acc[3][1] += xw3 * b0.y; acc[3][2] += xw3 * b0.z; acc[3][3] += xw3 * b0.w;
            acc[3][4] += xw3 * b1.x; acc[3][5] += xw3 * b1.y; acc[3][6] += xw3 * b1.z; acc[3][7] += xw3 * b1.w;
        }

        float* sbase = g_cs + (long)c * (NH * P_DIM * N_STATE) + (long)h * (P_DIM * N_STATE);
#pragma unroll
        for (int i = 0; i < 4; i++) {
            float* so = sbase + (p0 + i) * N_STATE + n0;
            *(float4*)&so[0] = make_float4(acc[i][0], acc[i][1], acc[i][2], acc[i][3]);
            *(float4*)&so[4] = make_float4(acc[i][4], acc[i][5], acc[i][6], acc[i][7]);
        }
    }
}

// ---------------- kernel 4b: propagate chunk-boundary states ----------------
__global__ void chunk_prop_kernel(const float* __restrict__ ssm_state_in,
                                  float* __restrict__ out_ssm) {
    long idx4 = (long)blockIdx.x * 256 + threadIdx.x;
    long idx = idx4 * 4;
    int h = (int)(idx >> 13);
    float4 s = *(const float4*)&ssm_state_in[idx];
#pragma unroll
    for (int c = 0; c < NC; c++) {
        float alpha = g_decay[(c * CHUNK + CHUNK - 1) * NH + h];
        float4 loc = *(const float4*)&g_cs[(long)c * 1048576 + idx];
        *(float4*)&g_cs[(long)c * 1048576 + idx] = s;
        s.x = alpha * s.x + loc.x;
        s.y = alpha * s.y + loc.y;
        s.z = alpha * s.z + loc.z;
        s.w = alpha * s.w + loc.w;
    }
    *(float4*)&out_ssm[idx] = s;
}

// ---------------- kernel 4c: correction y_t += decay(t) * C_t . s_in(chunk) ----------------
#define SP_STR 129
__global__ void chunk_corr_kernel() {
    int h = blockIdx.x;
    int c = blockIdx.y;
    int tid = threadIdx.x;
    int grp = h >> 4;

    extern __shared__ float sm[];
    float* S  = sm;                        // [64][SP_STR]
    float* Cs = sm + P_DIM * SP_STR;       // [32][128]
    float* Dec = Cs + CHUNK * N_STATE;     // [32]

    {
        const float* src = g_cs + (long)c * 1048576 + (long)h * (P_DIM * N_STATE);
        for (int i = tid; i < 2048; i += 256) {
            int pp = i >> 5, n4 = (i & 31) * 4;
            float4 v = *(const float4*)&src[pp * N_STATE + n4];
            float* d = &S[pp * SP_STR + n4];
            d[0] = v.x; d[1] = v.y; d[2] = v.z; d[3] = v.w;
        }
    }
    for (int i = tid; i < 1024; i += 256) {
        int tt = i >> 5, n4 = (i & 31) * 4;
        long base = (long)(c * CHUNK + tt) * CONV_DIM + D_INNER + D_STATE
                    + grp * N_STATE + n4;
        *(float4*)&Cs[tt * N_STATE + n4] = *(const float4*)&g_y[base];
    }
    if (tid < CHUNK) Dec[tid] = g_decay[(c * CHUNK + tid) * NH + h];
    __syncthreads();

    int p = tid & 63;
    int tb = (tid >> 6) * 8;
    float acc[8];
#pragma unroll
    for (int j = 0; j < 8; j++) acc[j] = 0.0f;

    const float* Sp = &S[p * SP_STR];
#pragma unroll 4
    for (int n = 0; n < N_STATE; n += 4) {
        float s0 = Sp[n], s1 = Sp[n + 1], s2 = Sp[n + 2], s3 = Sp[n + 3];
#pragma unroll
        for (int j = 0; j < 8; j++) {
            float4 c4 = *(const float4*)&Cs[(tb + j) * N_STATE + n];
            acc[j] += s0 * c4.x + s1 * c4.y + s2 * c4.z + s3 * c4.w;
        }
    }
#pragma unroll
    for (int j = 0; j < 8; j++) {
        int t = c * CHUNK + tb + j;
        long o = (long)t * D_INNER + h * P_DIM + p;
        g_ys[o] += Dec[tb + j] * acc[j];
    }
}

// ---------------- kernel 5: gate * silu + grouped RMSNorm (tf32-pre-rounded out) ----------------
__global__ void gnorm_kernel(const float* __restrict__ w) {
    int t = blockIdx.x, tid = threadIdx.x;
    __shared__ float red[8];
    __shared__ float sc_sh;
    for (int grp = 0; grp < 8; grp++) {
        int d0 = grp * 1024 + tid * 4;
        float4 gate4 = *(const float4*)&g_proj[(long)t * IN_OUT + d0];
        float4 ys4   = *(const float4*)&g_ys[(long)t * D_INNER + d0];
        float gx = ys4.x * siluf(gate4.x);
        float gy = ys4.y * siluf(gate4.y);
        float gz = ys4.z * siluf(gate4.z);
        float gw = ys4.w * siluf(gate4.w);
        float ss = gx * gx + gy * gy + gz * gz + gw * gw;
#pragma unroll
        for (int o = 16; o; o >>= 1) ss += __shfl_xor_sync(0xffffffffu, ss, o);
        if ((tid & 31) == 0) red[tid >> 5] = ss;
        __syncthreads();
        if (tid == 0) {
            float s = 0.0f;
#pragma unroll
            for (int i = 0; i < 8; i++) s += red[i];
            sc_sh = rsqrtf(s / 1024.0f + EPSV);
        }
        __syncthreads();
        float sc = sc_sh;
        float4 wf = *(const float4*)&w[d0];
        float4 o;
        o.x = f2tf_f(gx * sc * wf.x);
        o.y = f2tf_f(gy * sc * wf.y);
        o.z = f2tf_f(gz * sc * wf.z);
        o.w = f2tf_f(gw * sc * wf.w);
        *(float4*)&g_normed[(long)t * D_INNER + d0] = o;
        __syncthreads();
    }
}

// ---------------- launch ----------------
extern "C" void kernel_launch(void* const* d_in, const int* in_sizes, int n_in,
                              void* d_out, int out_size) {
    const float* hidden     = (const float*)d_in[0];
    const float* conv_state = (const float*)d_in[1];
    const float* ssm_state  = (const float*)d_in[2];
    const float* norm_w     = (const float*)d_in[3];
    const float* w_in       = (const float*)d_in[4];
    const float* conv_w     = (const float*)d_in[5];
    const float* conv_b     = (const float*)d_in[6];
    const float* A_log      = (const float*)d_in[7];
    const float* D_param    = (const float*)d_in[8];
    const float* dt_bias    = (const float*)d_in[9];
    const float* ssm_nw     = (const float*)d_in[10];
    const float* w_out      = (const float*)d_in[11];
    float* out = (float*)d_out;

    float* g_h_p;      cudaGetSymbolAddress((void**)&g_h_p, g_h);
    float* g_proj_p;   cudaGetSymbolAddress((void**)&g_proj_p, g_proj);
    float* g_normed_p; cudaGetSymbolAddress((void**)&g_normed_p, g_normed);

    constexpr int SMEM1 = 2 * (128 + 128) * 36 * 4;   // 73728
    constexpr int SMEM2 = 2 * (64 + 128) * 36 * 4;    // 55296
    constexpr int SMEM_CORR = (P_DIM * SP_STR + CHUNK * N_STATE + CHUNK) * 4;
    cudaFuncSetAttribute(gemm_tf32_kernel<128, 128, 2, 4>,
                         cudaFuncAttributeMaxDynamicSharedMemorySize, SMEM1);
    cudaFuncSetAttribute(gemm_tf32_kernel<64, 128, 2, 4>,
                         cudaFuncAttributeMaxDynamicSharedMemorySize, SMEM2);
    cudaFuncSetAttribute(chunk_corr_kernel,
                         cudaFuncAttributeMaxDynamicSharedMemorySize, SMEM_CORR);

    // 1) RMSNorm (tf32-pre-rounded output)
    rmsnorm_kernel<<<S_LEN, 256>>>(hidden, norm_w);

    // 2) in-proj
    gemm_tf32_kernel<128, 128, 2, 4><<<dim3(IN_OUT / 128, S_LEN / 128), 256, SMEM1>>>(
        g_h_p, w_in, g_proj_p, nullptr, S_LEN, IN_OUT, H_DIM);

    // 3) conv + silu + dtp + conv_state_out
    conv_kernel<<<S_LEN, 256>>>(conv_state, conv_w, conv_b, dt_bias, out + OUT_CONV);

    // 4) chunked SSM
    scan_chunk_kernel<<<dim3(NH, NC), 256>>>(A_log, D_param);
    chunk_prop_kernel<<<1024, 256>>>(ssm_state, out + OUT_SSM);
    chunk_corr_kernel<<<dim3(NH, NC), 256, SMEM_CORR>>>();

    // 5) gate + group norm (tf32-pre-rounded output)
    gnorm_kernel<<<S_LEN, 256>>>(ssm_nw);

    // 6) out-proj + residual
    gemm_tf32_kernel<64, 128, 2, 4><<<dim3(H_DIM / 128, S_LEN / 64), 256, SMEM2>>>(
        g_normed_p, w_out, out + OUT_HID, hidden, S_LEN, H_DIM, D_INNER);
}